// round 8
// baseline (speedup 1.0000x reference)
#include <cuda_runtime.h>
#include <math.h>

// Problem shape is fixed: N = 16384.
#define N_ELEM  16384
#define TN      256                         // tile dimension (rows=cols=threads)
#define NTILES  (N_ELEM / TN)               // 64
#define NTT     (NTILES * (NTILES + 1) / 2) // 2080 upper-triangle tiles
#define GRID    888                         // 148 SMs * 6 blocks: one resident wave

typedef unsigned long long ull;

// Scratch (no cudaMalloc allowed). Counters self-reset for graph replay.
__device__ float        g_partials[NTT];
__device__ unsigned int g_next = GRID;   // next tile to steal
__device__ unsigned int g_done = 0;      // finished blocks

__device__ __forceinline__ float tanhf_mufu(float x) {
    float y; asm("tanh.approx.f32 %0, %1;" : "=f"(y) : "f"(x)); return y;
}
__device__ __forceinline__ ull pack2(float lo, float hi) {
    ull r; asm("mov.b64 %0, {%1, %2};" : "=l"(r) : "f"(lo), "f"(hi)); return r;
}
__device__ __forceinline__ void unpack2(float& lo, float& hi, ull v) {
    asm("mov.b64 {%0, %1}, %2;" : "=f"(lo), "=f"(hi) : "l"(v));
}
__device__ __forceinline__ ull add2(ull a, ull b) {
    ull r; asm("add.rn.f32x2 %0, %1, %2;" : "=l"(r) : "l"(a), "l"(b)); return r;
}
__device__ __forceinline__ ull mul2(ull a, ull b) {
    ull r; asm("mul.rn.f32x2 %0, %1, %2;" : "=l"(r) : "l"(a), "l"(b)); return r;
}
__device__ __forceinline__ ull fma2(ull a, ull b, ull c) {
    ull r; asm("fma.rn.f32x2 %0, %1, %2, %3;" : "=l"(r) : "l"(a), "l"(b), "l"(c)); return r;
}

// Invert linear triangular tile index k -> (I, J), I <= J.
__device__ __forceinline__ void decode_tile(int k, int& I, int& J) {
    const float disc = 2.0f * (float)NTILES + 1.0f;
    int i = (int)((disc - sqrtf(disc * disc - 8.0f * (float)k)) * 0.5f);
    if (i < 0) i = 0;
    if (i >= NTILES) i = NTILES - 1;
    while (((i + 1) * NTILES - ((i + 1) * i) / 2) <= k) ++i;
    while ((i * NTILES - (i * (i - 1)) / 2) > k) --i;
    I = i;
    J = i + (k - (i * NTILES - (i * (i - 1)) / 2));
}

// Persistent kernel: each block steals TN x TN upper-triangle tiles.
// Per tile:  sum sigmoid(p_i p_j) |t_i - t_j| = 0.5*(A + B),
//   A = sum tanh(p_i * p_j/2)*|d|,  B = sum |d|   (diag tiles scaled 0.5).
__global__ __launch_bounds__(TN) void pair_persist_kernel(
    const float* __restrict__ yt, const float* __restrict__ yp,
    float* __restrict__ out)
{
    // Double-buffered column stage:
    // sh[b][m].x = packed (-t(2m), -t(2m+1)); .y = packed (p(2m)/2, p(2m+1)/2)
    __shared__ __align__(16) ulonglong2 sh[2][TN / 2];
    __shared__ float  red[TN / 32];
    __shared__ double dred[TN / 32];
    __shared__ unsigned int sh_next;
    __shared__ unsigned int sh_last;

    const int tid  = threadIdx.x;
    const int lane = tid & 31;
    const int wid  = tid >> 5;

    int k = blockIdx.x;          // initial tile (GRID <= NTT)
    int I, J;
    decode_tile(k, I, J);
    float tj = yt[J * TN + tid];
    float pj = yp[J * TN + tid];
    float ti = yt[I * TN + tid];
    float pi = yp[I * TN + tid];
    int buf = 0;

    while (true) {
        // Stage current tile's columns (interleaved packed layout -> LDS.128).
        {
            float* sf = (float*)sh[buf];
            const int m = tid >> 1, l = tid & 1;
            sf[4 * m + l]     = -tj;
            sf[4 * m + 2 + l] = 0.5f * pj;
        }
        const ull  tip  = pack2(ti, ti);
        const ull  pip  = pack2(pi, pi);
        const bool diag = (I == J);
        const int  kcur = k;

        // Steal next tile.
        if (tid == 0) sh_next = atomicAdd(&g_next, 1u);
        __syncthreads();                       // [B1] staging + sh_next visible
        const int k2 = (int)sh_next;

        // Prefetch next tile's data (LDGs overlap the compute below).
        if (k2 < NTT) {
            decode_tile(k2, I, J);
            tj = yt[J * TN + tid];
            pj = yp[J * TN + tid];
            ti = yt[I * TN + tid];
            pi = yp[I * TN + tid];
        }

        // MUFU-paced main loop over this tile's 256 columns.
        const ulonglong2* cs = sh[buf];
        ull A0 = 0ull, A1 = 0ull, B0 = 0ull, B1 = 0ull;
        #pragma unroll 8
        for (int m = 0; m < TN / 2; m += 2) {
            const ulonglong2 v0 = cs[m];
            const ulonglong2 v1 = cs[m + 1];
            const ull d0  = add2(tip, v0.x);             // (ti - t, ti - t')
            const ull d1  = add2(tip, v1.x);
            const ull ad0 = d0 & 0x7FFFFFFF7FFFFFFFull;  // |d| both lanes
            const ull ad1 = d1 & 0x7FFFFFFF7FFFFFFFull;
            const ull x0  = mul2(pip, v0.y);             // pi * p_j/2
            const ull x1  = mul2(pip, v1.y);
            float xa, xb, xc, xd;
            unpack2(xa, xb, x0);
            unpack2(xc, xd, x1);
            const ull th0 = pack2(tanhf_mufu(xa), tanhf_mufu(xb));
            const ull th1 = pack2(tanhf_mufu(xc), tanhf_mufu(xd));
            A0 = fma2(th0, ad0, A0);
            A1 = fma2(th1, ad1, A1);
            B0 = add2(B0, ad0);
            B1 = add2(B1, ad1);
        }

        float a0l, a0h, a1l, a1h, b0l, b0h, b1l, b1h;
        unpack2(a0l, a0h, A0); unpack2(a1l, a1h, A1);
        unpack2(b0l, b0h, B0); unpack2(b1l, b1h, B1);
        float P = 0.5f * (((a0l + a0h) + (a1l + a1h)) + ((b0l + b0h) + (b1l + b1h)));
        if (diag) P *= 0.5f;

        // Block reduction: warp butterfly + one shared stage.
        #pragma unroll
        for (int o = 16; o > 0; o >>= 1)
            P += __shfl_xor_sync(0xFFFFFFFFu, P, o);
        if (lane == 0) red[wid] = P;
        __syncthreads();                       // [B2]
        if (tid == 0) {
            float s = 0.f;
            #pragma unroll
            for (int w = 0; w < TN / 32; w++) s += red[w];
            g_partials[kcur] = s;
        }

        if (k2 >= NTT) break;
        k = k2;
        buf ^= 1;
    }

    // Completion: last block reduces all partials (fixed order -> deterministic).
    if (tid == 0) {
        __threadfence();
        unsigned int old = atomicAdd(&g_done, 1u);
        sh_last = (old == (unsigned)(GRID - 1)) ? 1u : 0u;
    }
    __syncthreads();

    if (sh_last) {
        __threadfence();
        double s = 0.0;
        for (int i = tid; i < NTT; i += TN)
            s += (double)g_partials[i];
        #pragma unroll
        for (int o = 16; o > 0; o >>= 1)
            s += __shfl_xor_sync(0xFFFFFFFFu, s, o);
        if (lane == 0) dred[wid] = s;
        __syncthreads();
        if (tid == 0) {
            double tot = 0.0;
            #pragma unroll
            for (int w = 0; w < TN / 32; w++) tot += dred[w];
            const double n2 = (double)N_ELEM * (double)N_ELEM;
            out[0] = (float)(-tot / n2);
            g_next = GRID;   // re-arm for next graph replay
            g_done = 0;
        }
    }
}

extern "C" void kernel_launch(void* const* d_in, const int* in_sizes, int n_in,
                              void* d_out, int out_size)
{
    const float* yt = (const float*)d_in[0];  // y_true
    const float* yp = (const float*)d_in[1];  // y_pred
    float* out = (float*)d_out;

    pair_persist_kernel<<<GRID, TN>>>(yt, yp, out);
}

// round 9
// speedup vs baseline: 1.0334x; 1.0334x over previous
#include <cuda_runtime.h>
#include <math.h>

// Problem shape is fixed: N = 16384.
#define N_ELEM  16384
#define TN      256                         // tile dimension (rows=cols)
#define NTILES  (N_ELEM / TN)               // 64
#define NTT     (NTILES * (NTILES + 1) / 2) // 2080 upper-triangle tiles
#define GRID    1184                        // 148 SMs * 8 resident blocks

typedef unsigned long long ull;

// Scratch (no cudaMalloc allowed). Counters self-reset for graph replay.
__device__ float        g_partials[NTT];
__device__ unsigned int g_next = GRID;   // next tile to steal
__device__ unsigned int g_done = 0;      // finished blocks

__device__ __forceinline__ float tanhf_mufu(float x) {
    float y; asm("tanh.approx.f32 %0, %1;" : "=f"(y) : "f"(x)); return y;
}
__device__ __forceinline__ ull pack2(float lo, float hi) {
    ull r; asm("mov.b64 %0, {%1, %2};" : "=l"(r) : "f"(lo), "f"(hi)); return r;
}
__device__ __forceinline__ void unpack2(float& lo, float& hi, ull v) {
    asm("mov.b64 {%0, %1}, %2;" : "=f"(lo), "=f"(hi) : "l"(v));
}
__device__ __forceinline__ ull add2(ull a, ull b) {
    ull r; asm("add.rn.f32x2 %0, %1, %2;" : "=l"(r) : "l"(a), "l"(b)); return r;
}
__device__ __forceinline__ ull mul2(ull a, ull b) {
    ull r; asm("mul.rn.f32x2 %0, %1, %2;" : "=l"(r) : "l"(a), "l"(b)); return r;
}
__device__ __forceinline__ ull fma2(ull a, ull b, ull c) {
    ull r; asm("fma.rn.f32x2 %0, %1, %2, %3;" : "=l"(r) : "l"(a), "l"(b), "l"(c)); return r;
}
__device__ __forceinline__ unsigned int smem_u32(const void* p) {
    unsigned int a;
    asm("{ .reg .u64 t; cvta.to.shared.u64 t, %1; cvt.u32.u64 %0, t; }"
        : "=r"(a) : "l"(p));
    return a;
}
__device__ __forceinline__ void cp_async16(unsigned int dst, const void* src) {
    asm volatile("cp.async.ca.shared.global [%0], [%1], 16;"
                 :: "r"(dst), "l"(src));
}
__device__ __forceinline__ void cp_commit() {
    asm volatile("cp.async.commit_group;");
}
__device__ __forceinline__ void cp_wait0() {
    asm volatile("cp.async.wait_group 0;");
}

// Invert linear triangular tile index k -> (I, J), I <= J.
__device__ __forceinline__ void decode_tile(int k, int& I, int& J) {
    const float disc = 2.0f * (float)NTILES + 1.0f;
    int i = (int)((disc - sqrtf(disc * disc - 8.0f * (float)k)) * 0.5f);
    if (i < 0) i = 0;
    if (i >= NTILES) i = NTILES - 1;
    while (((i + 1) * NTILES - ((i + 1) * i) / 2) <= k) ++i;
    while ((i * NTILES - (i * (i - 1)) / 2) > k) --i;
    I = i;
    J = i + (k - (i * NTILES - (i * (i - 1)) / 2));
}

// Smem stage per buffer: [ t_col(256) | p_col(256) | t_row(256) | p_row(256) ]
struct Stage { float tc[TN]; float pc[TN]; float tr[TN]; float pr[TN]; };

// Issue the 4 KB stage for tile (I,J): one 16B cp.async per thread.
__device__ __forceinline__ void issue_stage(
    Stage* st, const float* yt, const float* yp, int I, int J, int tid)
{
    const int q = tid & 63;                 // float4 index within a 256-array
    const int sel = tid >> 6;               // 0..3 selects which array
    const float* src;
    float* dst;
    if      (sel == 0) { src = yt + J * TN; dst = st->tc; }
    else if (sel == 1) { src = yp + J * TN; dst = st->pc; }
    else if (sel == 2) { src = yt + I * TN; dst = st->tr; }
    else               { src = yp + I * TN; dst = st->pr; }
    cp_async16(smem_u32(dst + 4 * q), src + 4 * q);
    cp_commit();
}

// Persistent work-stealing kernel over TN x TN upper-triangle tiles.
// Per tile: sum sigmoid(p_i p_j)|t_i - t_j| = 0.5*(A + B),
//   A = sum tanh(p_i/2 * p_j)*|d|,  B = sum |d|   (diag tiles scaled 0.5).
__global__ __launch_bounds__(TN, 8) void pair_persist_kernel(
    const float* __restrict__ yt, const float* __restrict__ yp,
    float* __restrict__ out)
{
    __shared__ __align__(16) Stage stage[2];
    __shared__ float  red[TN / 32];
    __shared__ double dred[TN / 32];
    __shared__ unsigned int sh_next;
    __shared__ unsigned int sh_last;

    const int tid  = threadIdx.x;
    const int lane = tid & 31;
    const int wid  = tid >> 5;

    int k = blockIdx.x;                     // initial tile (GRID <= NTT)
    int I, J;
    decode_tile(k, I, J);
    issue_stage(&stage[0], yt, yp, I, J, tid);
    int buf = 0;

    const ull cNEG1 = pack2(-1.0f, -1.0f);
    const ull cABS  = 0x7FFFFFFF7FFFFFFFull;

    while (true) {
        // Steal next tile while current stage finishes landing.
        if (tid == 0) sh_next = atomicAdd(&g_next, 1u);
        cp_wait0();
        __syncthreads();                    // stage[buf] + sh_next visible
        const int k2 = (int)sh_next;
        const int kcur = k;
        const bool diag = (I == J);

        // Row values for this thread.
        const float ti = stage[buf].tr[tid];
        const float pi = stage[buf].pr[tid];
        const ull tip  = pack2(ti, ti);
        const ull piph = pack2(0.5f * pi, 0.5f * pi);

        // Prefetch next tile's stage (overlaps the compute below).
        if (k2 < NTT) {
            decode_tile(k2, I, J);
            issue_stage(&stage[buf ^ 1], yt, yp, I, J, tid);
        }

        // MUFU-paced main loop over 256 columns (4 per iteration).
        const float4* t4 = (const float4*)stage[buf].tc;
        const float4* p4 = (const float4*)stage[buf].pc;
        ull A0 = 0ull, A1 = 0ull, B0 = 0ull, B1 = 0ull;
        #pragma unroll 8
        for (int g = 0; g < TN / 4; g++) {
            const float4 tv = t4[g];
            const float4 pv = p4[g];
            const ull tj0 = pack2(tv.x, tv.y);
            const ull tj1 = pack2(tv.z, tv.w);
            const ull pj0 = pack2(pv.x, pv.y);
            const ull pj1 = pack2(pv.z, pv.w);
            const ull d0  = fma2(tj0, cNEG1, tip);   // (ti - tj) x2
            const ull d1  = fma2(tj1, cNEG1, tip);
            const ull ad0 = d0 & cABS;               // |d|
            const ull ad1 = d1 & cABS;
            const ull x0  = mul2(piph, pj0);         // (pi/2) * pj
            const ull x1  = mul2(piph, pj1);
            float xa, xb, xc, xd;
            unpack2(xa, xb, x0);
            unpack2(xc, xd, x1);
            const ull th0 = pack2(tanhf_mufu(xa), tanhf_mufu(xb));
            const ull th1 = pack2(tanhf_mufu(xc), tanhf_mufu(xd));
            A0 = fma2(th0, ad0, A0);
            A1 = fma2(th1, ad1, A1);
            B0 = add2(B0, ad0);
            B1 = add2(B1, ad1);
        }

        float a0l, a0h, a1l, a1h, b0l, b0h, b1l, b1h;
        unpack2(a0l, a0h, A0); unpack2(a1l, a1h, A1);
        unpack2(b0l, b0h, B0); unpack2(b1l, b1h, B1);
        float P = 0.5f * (((a0l + a0h) + (a1l + a1h)) + ((b0l + b0h) + (b1l + b1h)));
        if (diag) P *= 0.5f;

        // Block reduction: warp butterfly + one shared stage.
        #pragma unroll
        for (int o = 16; o > 0; o >>= 1)
            P += __shfl_xor_sync(0xFFFFFFFFu, P, o);
        if (lane == 0) red[wid] = P;
        __syncthreads();
        if (tid == 0) {
            float s = 0.f;
            #pragma unroll
            for (int w = 0; w < TN / 32; w++) s += red[w];
            g_partials[kcur] = s;           // deterministic per-tile value
        }

        if (k2 >= NTT) break;
        k = k2;
        buf ^= 1;
    }

    // Completion: last block reduces all partials (fixed order -> deterministic).
    if (tid == 0) {
        __threadfence();
        unsigned int old = atomicAdd(&g_done, 1u);
        sh_last = (old == (unsigned)(GRID - 1)) ? 1u : 0u;
    }
    __syncthreads();

    if (sh_last) {
        __threadfence();
        double s = 0.0;
        for (int i = tid; i < NTT; i += TN)
            s += (double)g_partials[i];
        #pragma unroll
        for (int o = 16; o > 0; o >>= 1)
            s += __shfl_xor_sync(0xFFFFFFFFu, s, o);
        if (lane == 0) dred[wid] = s;
        __syncthreads();
        if (tid == 0) {
            double tot = 0.0;
            #pragma unroll
            for (int w = 0; w < TN / 32; w++) tot += dred[w];
            const double n2 = (double)N_ELEM * (double)N_ELEM;
            out[0] = (float)(-tot / n2);
            g_next = GRID;                  // re-arm for next graph replay
            g_done = 0;
        }
    }
}

extern "C" void kernel_launch(void* const* d_in, const int* in_sizes, int n_in,
                              void* d_out, int out_size)
{
    const float* yt = (const float*)d_in[0];  // y_true
    const float* yp = (const float*)d_in[1];  // y_pred
    float* out = (float*)d_out;

    pair_persist_kernel<<<GRID, TN>>>(yt, yp, out);
}

// round 10
// speedup vs baseline: 1.0968x; 1.0613x over previous
#include <cuda_runtime.h>
#include <math.h>

// Problem shape is fixed: N = 16384.
#define N_ELEM  16384
#define TN      256                         // tile dimension (rows=cols=threads)
#define NTILES  (N_ELEM / TN)               // 64
#define NBLOCKS (NTILES * (NTILES + 1) / 2) // 2080 upper-triangle tiles

typedef unsigned long long ull;
typedef unsigned int uint;

// Scratch for deterministic two-stage reduction (no cudaMalloc allowed).
__device__ float        g_partials[NBLOCKS];
__device__ unsigned int g_arrive = 0;       // reset by last block each launch

// ---- f16x2 / f32x2 helpers -------------------------------------------------
__device__ __forceinline__ uint cvt2h(float hi, float lo) {   // pack {lo,hi} f16x2
    uint r; asm("cvt.rn.f16x2.f32 %0, %1, %2;" : "=r"(r) : "f"(hi), "f"(lo)); return r;
}
__device__ __forceinline__ uint hsub2(uint a, uint b) {
    uint r; asm("sub.f16x2 %0, %1, %2;" : "=r"(r) : "r"(a), "r"(b)); return r;
}
__device__ __forceinline__ uint hmul2(uint a, uint b) {
    uint r; asm("mul.f16x2 %0, %1, %2;" : "=r"(r) : "r"(a), "r"(b)); return r;
}
__device__ __forceinline__ uint hadd2(uint a, uint b) {
    uint r; asm("add.f16x2 %0, %1, %2;" : "=r"(r) : "r"(a), "r"(b)); return r;
}
__device__ __forceinline__ uint hfma2(uint a, uint b, uint c) {
    uint r; asm("fma.rn.f16x2 %0, %1, %2, %3;" : "=r"(r) : "r"(a), "r"(b), "r"(c)); return r;
}
__device__ __forceinline__ uint htanh2(uint x) {              // 2 tanh per MUFU issue
    uint r; asm("tanh.approx.f16x2 %0, %1;" : "=r"(r) : "r"(x)); return r;
}
__device__ __forceinline__ void h2_to_f32(float& a, float& b, uint p) {
    asm("{\n\t.reg .b16 l, h;\n\tmov.b32 {l, h}, %2;\n\t"
        "cvt.f32.f16 %0, l;\n\tcvt.f32.f16 %1, h;\n\t}"
        : "=f"(a), "=f"(b) : "r"(p));
}
__device__ __forceinline__ ull pack2(float lo, float hi) {
    ull r; asm("mov.b64 %0, {%1, %2};" : "=l"(r) : "f"(lo), "f"(hi)); return r;
}
__device__ __forceinline__ void unpack2(float& lo, float& hi, ull v) {
    asm("mov.b64 {%0, %1}, %2;" : "=f"(lo), "=f"(hi) : "l"(v));
}
__device__ __forceinline__ ull add2(ull a, ull b) {
    ull r; asm("add.rn.f32x2 %0, %1, %2;" : "=l"(r) : "l"(a), "l"(b)); return r;
}

// One block = one TN x TN tile (I,J) of the upper triangle (I <= J).
// Per pair (i,j): term = (1 + tanh(p_i/2 * p_j)) * |t_i - t_j| = 2*sigmoid(p_i p_j)*|d|
// Tile partial = 0.5 * sum(term); diagonal tiles scaled by an extra 0.5
// (diag pairs contribute 0; tile is symmetric).
__global__ __launch_bounds__(TN) void pair_tile_kernel(
    const float* __restrict__ yt, const float* __restrict__ yp,
    float* __restrict__ out)
{
    // Column stage: uint4 group g holds packs 2g,2g+1:
    //   { th2(2g), ph2(2g), th2(2g+1), ph2(2g+1) }
    // th2(m) = f16x2 (t_{2m}, t_{2m+1});  ph2(m) = f16x2 (p_{2m}/2, p_{2m+1}/2)
    __shared__ __align__(16) uint4 sh[TN / 4];
    __shared__ float  red[TN / 32];
    __shared__ double dred[TN / 32];
    __shared__ unsigned int is_last;

    // Invert linear triangular block index k -> (I, J), I <= J.
    const int k = blockIdx.x;
    const float disc = 2.0f * (float)NTILES + 1.0f;
    int I = (int)((disc - sqrtf(disc * disc - 8.0f * (float)k)) * 0.5f);
    if (I < 0) I = 0;
    if (I >= NTILES) I = NTILES - 1;
    while (((I + 1) * NTILES - ((I + 1) * I) / 2) <= k) ++I;
    while ((I * NTILES - (I * (I - 1)) / 2) > k) --I;
    const int J = I + (k - (I * NTILES - (I * (I - 1)) / 2));

    const int tid  = threadIdx.x;
    const int lane = tid & 31;
    const int wid  = tid >> 5;

    // Row values for this thread (f32 load, broadcast-packed to f16x2).
    const int ig = I * TN + tid;
    const float ti = yt[ig];
    const float pi = yp[ig];
    const uint ti2  = cvt2h(ti, ti);
    const uint pih2 = cvt2h(0.5f * pi, 0.5f * pi);

    // Stage column tile: threads 0..127 each build one f16x2 pack (2 columns).
    if (tid < TN / 2) {
        const float2 tc = *(const float2*)(yt + J * TN + 2 * tid);
        const float2 pc = *(const float2*)(yp + J * TN + 2 * tid);
        const uint th2 = cvt2h(tc.y, tc.x);
        const uint ph2 = cvt2h(0.5f * pc.y, 0.5f * pc.x);
        uint* sw = (uint*)sh;
        const int g = tid >> 1, s = tid & 1;
        sw[4 * g + 2 * s]     = th2;
        sw[4 * g + 2 * s + 1] = ph2;
    }
    __syncthreads();

    // Co-saturated MUFU/FMA main loop: 8 columns (4 f16x2 packs) per iteration.
    ull A0 = 0ull, A1 = 0ull;
    #pragma unroll 8
    for (int g = 0; g < TN / 8; g++) {
        const uint4 w0 = sh[2 * g];
        const uint4 w1 = sh[2 * g + 1];

        const uint d_a  = hsub2(ti2, w0.x);
        const uint d_b  = hsub2(ti2, w0.z);
        const uint d_c  = hsub2(ti2, w1.x);
        const uint d_d  = hsub2(ti2, w1.z);
        const uint ad_a = d_a & 0x7FFF7FFFu;     // |d| (f16 sign bits)
        const uint ad_b = d_b & 0x7FFF7FFFu;
        const uint ad_c = d_c & 0x7FFF7FFFu;
        const uint ad_d = d_d & 0x7FFF7FFFu;
        const uint x_a  = hmul2(pih2, w0.y);     // (p_i/2) * p_j
        const uint x_b  = hmul2(pih2, w0.w);
        const uint x_c  = hmul2(pih2, w1.y);
        const uint x_d  = hmul2(pih2, w1.w);
        const uint s_a  = htanh2(x_a);           // 2 tanh per MUFU issue
        const uint s_b  = htanh2(x_b);
        const uint s_c  = htanh2(x_c);
        const uint s_d  = htanh2(x_d);
        const uint p_a  = hfma2(s_a, ad_a, ad_a); // (1+tanh)*|d|
        const uint p_b  = hfma2(s_b, ad_b, ad_b);
        const uint p_c  = hfma2(s_c, ad_c, ad_c);
        const uint p_d  = hfma2(s_d, ad_d, ad_d);

        // Depth-2 f16 partial-sum tree (magnitude <= 8), then f32x2 accumulate.
        const uint ps0 = hadd2(p_a, p_b);
        const uint ps1 = hadd2(p_c, p_d);
        const uint ps  = hadd2(ps0, ps1);
        float flo, fhi;
        h2_to_f32(flo, fhi, ps);
        if (g & 1) A1 = add2(A1, pack2(flo, fhi));
        else       A0 = add2(A0, pack2(flo, fhi));
    }

    float a0l, a0h, a1l, a1h;
    unpack2(a0l, a0h, A0);
    unpack2(a1l, a1h, A1);
    float P = 0.5f * ((a0l + a0h) + (a1l + a1h));  // term = 2*sigma*|d|
    if (I == J) P *= 0.5f;

    // Block reduction: warp butterfly + one shared stage.
    #pragma unroll
    for (int o = 16; o > 0; o >>= 1)
        P += __shfl_xor_sync(0xFFFFFFFFu, P, o);
    if (lane == 0) red[wid] = P;
    __syncthreads();

    // Publish partial; last-arriving block does the (deterministic) final sum.
    if (tid == 0) {
        float s = 0.f;
        #pragma unroll
        for (int w = 0; w < TN / 32; w++) s += red[w];
        g_partials[k] = s;
        __threadfence();
        unsigned int old = atomicAdd(&g_arrive, 1u);
        is_last = (old == (unsigned)(NBLOCKS - 1)) ? 1u : 0u;
    }
    __syncthreads();

    if (is_last) {
        __threadfence();
        double s = 0.0;
        for (int i = tid; i < NBLOCKS; i += TN)   // fixed order -> deterministic
            s += (double)g_partials[i];
        #pragma unroll
        for (int o = 16; o > 0; o >>= 1)
            s += __shfl_xor_sync(0xFFFFFFFFu, s, o);
        if (lane == 0) dred[wid] = s;
        __syncthreads();
        if (tid == 0) {
            double tot = 0.0;
            #pragma unroll
            for (int w = 0; w < TN / 32; w++) tot += dred[w];
            const double n2 = (double)N_ELEM * (double)N_ELEM;
            out[0] = (float)(-tot / n2);
            g_arrive = 0;                          // re-arm for next graph replay
        }
    }
}

extern "C" void kernel_launch(void* const* d_in, const int* in_sizes, int n_in,
                              void* d_out, int out_size)
{
    const float* yt = (const float*)d_in[0];  // y_true
    const float* yp = (const float*)d_in[1];  // y_pred
    float* out = (float*)d_out;

    pair_tile_kernel<<<NBLOCKS, TN>>>(yt, yp, out);
}

// round 11
// speedup vs baseline: 1.0985x; 1.0016x over previous
#include <cuda_runtime.h>
#include <math.h>

// Problem shape is fixed: N = 16384.
#define N_ELEM  16384
#define TN      256                         // tile dimension (rows=cols=threads)
#define NTILES  (N_ELEM / TN)               // 64
#define NBLOCKS (NTILES * (NTILES + 1) / 2) // 2080 upper-triangle tiles

typedef unsigned long long ull;
typedef unsigned int uint;

// Scratch for deterministic two-stage reduction (no cudaMalloc allowed).
__device__ float        g_partials[NBLOCKS];
__device__ unsigned int g_arrive = 0;       // reset by last block each launch

// ---- f16x2 / f32x2 helpers -------------------------------------------------
__device__ __forceinline__ uint cvt2h(float hi, float lo) {   // pack {lo,hi} f16x2
    uint r; asm("cvt.rn.f16x2.f32 %0, %1, %2;" : "=r"(r) : "f"(hi), "f"(lo)); return r;
}
__device__ __forceinline__ uint hsub2(uint a, uint b) {
    uint r; asm("sub.f16x2 %0, %1, %2;" : "=r"(r) : "r"(a), "r"(b)); return r;
}
__device__ __forceinline__ uint hmul2(uint a, uint b) {
    uint r; asm("mul.f16x2 %0, %1, %2;" : "=r"(r) : "r"(a), "r"(b)); return r;
}
__device__ __forceinline__ uint hadd2(uint a, uint b) {
    uint r; asm("add.f16x2 %0, %1, %2;" : "=r"(r) : "r"(a), "r"(b)); return r;
}
__device__ __forceinline__ uint hfma2(uint a, uint b, uint c) {
    uint r; asm("fma.rn.f16x2 %0, %1, %2, %3;" : "=r"(r) : "r"(a), "r"(b), "r"(c)); return r;
}
__device__ __forceinline__ uint htanh2(uint x) {              // 2 tanh per MUFU issue
    uint r; asm("tanh.approx.f16x2 %0, %1;" : "=r"(r) : "r"(x)); return r;
}
__device__ __forceinline__ void h2_to_f32(float& a, float& b, uint p) {
    asm("{\n\t.reg .b16 l, h;\n\tmov.b32 {l, h}, %2;\n\t"
        "cvt.f32.f16 %0, l;\n\tcvt.f32.f16 %1, h;\n\t}"
        : "=f"(a), "=f"(b) : "r"(p));
}
__device__ __forceinline__ ull pack2(float lo, float hi) {
    ull r; asm("mov.b64 %0, {%1, %2};" : "=l"(r) : "f"(lo), "f"(hi)); return r;
}
__device__ __forceinline__ void unpack2(float& lo, float& hi, ull v) {
    asm("mov.b64 {%0, %1}, %2;" : "=f"(lo), "=f"(hi) : "l"(v));
}
__device__ __forceinline__ ull add2(ull a, ull b) {
    ull r; asm("add.rn.f32x2 %0, %1, %2;" : "=l"(r) : "l"(a), "l"(b)); return r;
}

// One block = one TN x TN tile (I,J) of the upper triangle (I <= J).
// Per pair (i,j): term = (1 + tanh(p_i/2 * p_j)) * |t_i - t_j| = 2*sigmoid(p_i p_j)*|d|
// Tile partial = 0.5 * sum(term); diagonal tiles scaled by an extra 0.5
// (diag pairs contribute 0; tile is symmetric).
__global__ __launch_bounds__(TN) void pair_tile_kernel(
    const float* __restrict__ yt, const float* __restrict__ yp,
    float* __restrict__ out)
{
    // Column stage: uint4 group g holds packs 2g,2g+1:
    //   { th2(2g), ph2(2g), th2(2g+1), ph2(2g+1) }
    // th2(m) = f16x2 (t_{2m}, t_{2m+1});  ph2(m) = f16x2 (p_{2m}/2, p_{2m+1}/2)
    __shared__ __align__(16) uint4 sh[TN / 4];
    __shared__ float  red[TN / 32];
    __shared__ double dred[TN / 32];
    __shared__ unsigned int is_last;

    // Invert linear triangular block index k -> (I, J), I <= J.
    const int k = blockIdx.x;
    const float disc = 2.0f * (float)NTILES + 1.0f;
    int I = (int)((disc - sqrtf(disc * disc - 8.0f * (float)k)) * 0.5f);
    if (I < 0) I = 0;
    if (I >= NTILES) I = NTILES - 1;
    while (((I + 1) * NTILES - ((I + 1) * I) / 2) <= k) ++I;
    while ((I * NTILES - (I * (I - 1)) / 2) > k) --I;
    const int J = I + (k - (I * NTILES - (I * (I - 1)) / 2));

    const int tid  = threadIdx.x;
    const int lane = tid & 31;
    const int wid  = tid >> 5;

    // Row values for this thread (f32 load, broadcast-packed to f16x2).
    const int ig = I * TN + tid;
    const float ti = yt[ig];
    const float pi = yp[ig];
    const uint ti2  = cvt2h(ti, ti);
    const uint pih2 = cvt2h(0.5f * pi, 0.5f * pi);

    // Stage column tile: threads 0..127 each build one f16x2 pack (2 columns).
    if (tid < TN / 2) {
        const float2 tc = *(const float2*)(yt + J * TN + 2 * tid);
        const float2 pc = *(const float2*)(yp + J * TN + 2 * tid);
        const uint th2 = cvt2h(tc.y, tc.x);
        const uint ph2 = cvt2h(0.5f * pc.y, 0.5f * pc.x);
        uint* sw = (uint*)sh;
        const int g = tid >> 1, s = tid & 1;
        sw[4 * g + 2 * s]     = th2;
        sw[4 * g + 2 * s + 1] = ph2;
    }
    __syncthreads();

    // Co-saturated MUFU/FMA main loop: 8 columns (4 f16x2 packs) per iteration.
    ull A0 = 0ull, A1 = 0ull;
    #pragma unroll 8
    for (int g = 0; g < TN / 8; g++) {
        const uint4 w0 = sh[2 * g];
        const uint4 w1 = sh[2 * g + 1];

        const uint d_a  = hsub2(ti2, w0.x);
        const uint d_b  = hsub2(ti2, w0.z);
        const uint d_c  = hsub2(ti2, w1.x);
        const uint d_d  = hsub2(ti2, w1.z);
        const uint ad_a = d_a & 0x7FFF7FFFu;     // |d| (f16 sign bits)
        const uint ad_b = d_b & 0x7FFF7FFFu;
        const uint ad_c = d_c & 0x7FFF7FFFu;
        const uint ad_d = d_d & 0x7FFF7FFFu;
        const uint x_a  = hmul2(pih2, w0.y);     // (p_i/2) * p_j
        const uint x_b  = hmul2(pih2, w0.w);
        const uint x_c  = hmul2(pih2, w1.y);
        const uint x_d  = hmul2(pih2, w1.w);
        const uint s_a  = htanh2(x_a);           // 2 tanh per MUFU issue
        const uint s_b  = htanh2(x_b);
        const uint s_c  = htanh2(x_c);
        const uint s_d  = htanh2(x_d);
        const uint p_a  = hfma2(s_a, ad_a, ad_a); // (1+tanh)*|d|
        const uint p_b  = hfma2(s_b, ad_b, ad_b);
        const uint p_c  = hfma2(s_c, ad_c, ad_c);
        const uint p_d  = hfma2(s_d, ad_d, ad_d);

        // Depth-2 f16 partial-sum tree (magnitude <= 8), then f32x2 accumulate.
        const uint ps0 = hadd2(p_a, p_b);
        const uint ps1 = hadd2(p_c, p_d);
        const uint ps  = hadd2(ps0, ps1);
        float flo, fhi;
        h2_to_f32(flo, fhi, ps);
        if (g & 1) A1 = add2(A1, pack2(flo, fhi));
        else       A0 = add2(A0, pack2(flo, fhi));
    }

    float a0l, a0h, a1l, a1h;
    unpack2(a0l, a0h, A0);
    unpack2(a1l, a1h, A1);
    float P = 0.5f * ((a0l + a0h) + (a1l + a1h));  // term = 2*sigma*|d|
    if (I == J) P *= 0.5f;

    // Block reduction: warp butterfly + one shared stage.
    #pragma unroll
    for (int o = 16; o > 0; o >>= 1)
        P += __shfl_xor_sync(0xFFFFFFFFu, P, o);
    if (lane == 0) red[wid] = P;
    __syncthreads();

    // Publish partial; last-arriving block does the (deterministic) final sum.
    if (tid == 0) {
        float s = 0.f;
        #pragma unroll
        for (int w = 0; w < TN / 32; w++) s += red[w];
        g_partials[k] = s;
        __threadfence();
        unsigned int old = atomicAdd(&g_arrive, 1u);
        is_last = (old == (unsigned)(NBLOCKS - 1)) ? 1u : 0u;
    }
    __syncthreads();

    if (is_last) {
        __threadfence();
        double s = 0.0;
        for (int i = tid; i < NBLOCKS; i += TN)   // fixed order -> deterministic
            s += (double)g_partials[i];
        #pragma unroll
        for (int o = 16; o > 0; o >>= 1)
            s += __shfl_xor_sync(0xFFFFFFFFu, s, o);
        if (lane == 0) dred[wid] = s;
        __syncthreads();
        if (tid == 0) {
            double tot = 0.0;
            #pragma unroll
            for (int w = 0; w < TN / 32; w++) tot += dred[w];
            const double n2 = (double)N_ELEM * (double)N_ELEM;
            out[0] = (float)(-tot / n2);
            g_arrive = 0;                          // re-arm for next graph replay
        }
    }
}

extern "C" void kernel_launch(void* const* d_in, const int* in_sizes, int n_in,
                              void* d_out, int out_size)
{
    const float* yt = (const float*)d_in[0];  // y_true
    const float* yp = (const float*)d_in[1];  // y_pred
    float* out = (float*)d_out;

    pair_tile_kernel<<<NBLOCKS, TN>>>(yt, yp, out);
}

// round 12
// speedup vs baseline: 1.1048x; 1.0057x over previous
#include <cuda_runtime.h>
#include <math.h>

// Problem shape is fixed: N = 16384.
#define N_ELEM  16384
#define TN      256                         // tile dimension (rows=cols=threads)
#define NTILES  (N_ELEM / TN)               // 64
#define NBLOCKS (NTILES * (NTILES + 1) / 2) // 2080 upper-triangle tiles

typedef unsigned long long ull;
typedef unsigned int uint;

// Scratch for deterministic two-stage reduction (no cudaMalloc allowed).
__device__ float        g_partials[NBLOCKS];
__device__ unsigned int g_arrive = 0;       // reset by last block each launch

// ---- f16x2 helpers ---------------------------------------------------------
__device__ __forceinline__ uint cvt2h(float hi, float lo) {   // pack {lo,hi} f16x2
    uint r; asm("cvt.rn.f16x2.f32 %0, %1, %2;" : "=r"(r) : "f"(hi), "f"(lo)); return r;
}
__device__ __forceinline__ uint hsub2(uint a, uint b) {
    uint r; asm("sub.f16x2 %0, %1, %2;" : "=r"(r) : "r"(a), "r"(b)); return r;
}
__device__ __forceinline__ uint hmul2(uint a, uint b) {
    uint r; asm("mul.f16x2 %0, %1, %2;" : "=r"(r) : "r"(a), "r"(b)); return r;
}
__device__ __forceinline__ uint hadd2(uint a, uint b) {
    uint r; asm("add.f16x2 %0, %1, %2;" : "=r"(r) : "r"(a), "r"(b)); return r;
}
__device__ __forceinline__ uint hfma2(uint a, uint b, uint c) {
    uint r; asm("fma.rn.f16x2 %0, %1, %2, %3;" : "=r"(r) : "r"(a), "r"(b), "r"(c)); return r;
}
__device__ __forceinline__ uint htanh2(uint x) {
    uint r; asm("tanh.approx.f16x2 %0, %1;" : "=r"(r) : "r"(x)); return r;
}
__device__ __forceinline__ void h2_to_f32(float& a, float& b, uint p) {
    asm("{\n\t.reg .b16 l, h;\n\tmov.b32 {l, h}, %2;\n\t"
        "cvt.f32.f16 %0, l;\n\tcvt.f32.f16 %1, h;\n\t}"
        : "=f"(a), "=f"(b) : "r"(p));
}

// One block = one TN x TN tile (I,J) of the upper triangle (I <= J).
// Per pair (i,j): term = (1 + tanh(p_i/2 * p_j)) * |t_i - t_j| = 2*sigmoid(p_i p_j)*|d|
// Tile partial = 0.5 * sum(term); diagonal tiles get an extra 0.5
// (diag pairs contribute 0; tile is symmetric).
// A-chains accumulate tanh*|d|, B-chains |d|; whole tile kept in f16x2 chains
// (32 terms/lane, |sum| <= 32 — f16-safe; RNE rounding unbiased, cancels in mean).
__global__ __launch_bounds__(TN) void pair_tile_kernel(
    const float* __restrict__ yt, const float* __restrict__ yp,
    float* __restrict__ out)
{
    // Column stage: uint4 group g holds packs 2g,2g+1:
    //   { th2(2g), ph2(2g), th2(2g+1), ph2(2g+1) }
    // th2(m) = f16x2 (t_{2m}, t_{2m+1});  ph2(m) = f16x2 (p_{2m}/2, p_{2m+1}/2)
    __shared__ __align__(16) uint4 sh[TN / 4];
    __shared__ float  red[TN / 32];
    __shared__ double dred[TN / 32];
    __shared__ unsigned int is_last;

    // Invert linear triangular block index k -> (I, J), I <= J.
    const int k = blockIdx.x;
    const float disc = 2.0f * (float)NTILES + 1.0f;
    int I = (int)((disc - sqrtf(disc * disc - 8.0f * (float)k)) * 0.5f);
    if (I < 0) I = 0;
    if (I >= NTILES) I = NTILES - 1;
    while (((I + 1) * NTILES - ((I + 1) * I) / 2) <= k) ++I;
    while ((I * NTILES - (I * (I - 1)) / 2) > k) --I;
    const int J = I + (k - (I * NTILES - (I * (I - 1)) / 2));

    const int tid  = threadIdx.x;
    const int lane = tid & 31;
    const int wid  = tid >> 5;

    // Row values for this thread (f32 load, broadcast-packed to f16x2).
    const int ig = I * TN + tid;
    const float ti = yt[ig];
    const float pi = yp[ig];
    const uint ti2  = cvt2h(ti, ti);
    const uint pih2 = cvt2h(0.5f * pi, 0.5f * pi);

    // Stage column tile: threads 0..127 each build one f16x2 pack (2 columns).
    if (tid < TN / 2) {
        const float2 tc = *(const float2*)(yt + J * TN + 2 * tid);
        const float2 pc = *(const float2*)(yp + J * TN + 2 * tid);
        const uint th2 = cvt2h(tc.y, tc.x);
        const uint ph2 = cvt2h(0.5f * pc.y, 0.5f * pc.x);
        uint* sw = (uint*)sh;
        const int g = tid >> 1, s = tid & 1;
        sw[4 * g + 2 * s]     = th2;
        sw[4 * g + 2 * s + 1] = ph2;
    }
    __syncthreads();

    // MUFU-wall main loop: 8 columns (4 f16x2 packs) per iteration.
    // 26 issue slots per iter vs 64-cyc MUFU floor (4 x tanh.f16x2 @ rt16).
    uint Aa = 0u, Ab = 0u, Ac = 0u, Ad = 0u;   // f16x2 +0.0 = 0x0000
    uint Ba = 0u, Bb = 0u, Bc = 0u, Bd = 0u;
    #pragma unroll 16
    for (int g = 0; g < TN / 8; g++) {
        const uint4 w0 = sh[2 * g];
        const uint4 w1 = sh[2 * g + 1];

        const uint ad_a = hsub2(ti2, w0.x) & 0x7FFF7FFFu;  // |t_i - t_j|
        const uint ad_b = hsub2(ti2, w0.z) & 0x7FFF7FFFu;
        const uint ad_c = hsub2(ti2, w1.x) & 0x7FFF7FFFu;
        const uint ad_d = hsub2(ti2, w1.z) & 0x7FFF7FFFu;
        const uint s_a  = htanh2(hmul2(pih2, w0.y));       // tanh(p_i p_j / 2)
        const uint s_b  = htanh2(hmul2(pih2, w0.w));
        const uint s_c  = htanh2(hmul2(pih2, w1.y));
        const uint s_d  = htanh2(hmul2(pih2, w1.w));
        Aa = hfma2(s_a, ad_a, Aa);                         // += tanh * |d|
        Ab = hfma2(s_b, ad_b, Ab);
        Ac = hfma2(s_c, ad_c, Ac);
        Ad = hfma2(s_d, ad_d, Ad);
        Ba = hadd2(Ba, ad_a);                              // += |d|
        Bb = hadd2(Bb, ad_b);
        Bc = hadd2(Bc, ad_c);
        Bd = hadd2(Bd, ad_d);
    }

    // Tile epilogue: combine 8 f16x2 chains -> f32.
    const uint At = hadd2(hadd2(Aa, Ab), hadd2(Ac, Ad));   // |lane| <= 128
    const uint Bt = hadd2(hadd2(Ba, Bb), hadd2(Bc, Bd));
    float al, ah, bl, bh;
    h2_to_f32(al, ah, At);
    h2_to_f32(bl, bh, Bt);
    float P = 0.5f * ((al + ah) + (bl + bh));              // term = 2*sigma*|d|
    if (I == J) P *= 0.5f;

    // Block reduction: warp butterfly + one shared stage.
    #pragma unroll
    for (int o = 16; o > 0; o >>= 1)
        P += __shfl_xor_sync(0xFFFFFFFFu, P, o);
    if (lane == 0) red[wid] = P;
    __syncthreads();

    // Publish partial; last-arriving block does the (deterministic) final sum.
    if (tid == 0) {
        float s = 0.f;
        #pragma unroll
        for (int w = 0; w < TN / 32; w++) s += red[w];
        g_partials[k] = s;
        __threadfence();
        unsigned int old = atomicAdd(&g_arrive, 1u);
        is_last = (old == (unsigned)(NBLOCKS - 1)) ? 1u : 0u;
    }
    __syncthreads();

    if (is_last) {
        __threadfence();
        double s = 0.0;
        for (int i = tid; i < NBLOCKS; i += TN)   // fixed order -> deterministic
            s += (double)g_partials[i];
        #pragma unroll
        for (int o = 16; o > 0; o >>= 1)
            s += __shfl_xor_sync(0xFFFFFFFFu, s, o);
        if (lane == 0) dred[wid] = s;
        __syncthreads();
        if (tid == 0) {
            double tot = 0.0;
            #pragma unroll
            for (int w = 0; w < TN / 32; w++) tot += dred[w];
            const double n2 = (double)N_ELEM * (double)N_ELEM;
            out[0] = (float)(-tot / n2);
            g_arrive = 0;                          // re-arm for next graph replay
        }
    }
}

extern "C" void kernel_launch(void* const* d_in, const int* in_sizes, int n_in,
                              void* d_out, int out_size)
{
    const float* yt = (const float*)d_in[0];  // y_true
    const float* yp = (const float*)d_in[1];  // y_pred
    float* out = (float*)d_out;

    pair_tile_kernel<<<NBLOCKS, TN>>>(yt, yp, out);
}